// round 5
// baseline (speedup 1.0000x reference)
#include <cuda_runtime.h>

#define IN_DIM    20
#define HID       6
#define OUT_DIM   6
#define THREADS   128
#define NWARPS    (THREADS / 32)
#define WT_ROWS   64                         // rows per warp-tile (2 per lane)
#define WT_F4     (WT_ROWS * IN_DIM / 4)     // 320 float4 per warp-tile
#define F4_PL     (WT_F4 / 32)               // 10 float4 per lane
#define WT_FLOATS (WT_ROWS * IN_DIM)         // 1280 floats = 5120 B

__device__ __forceinline__ unsigned smem_u32(const void* p) {
    return (unsigned)__cvta_generic_to_shared(p);
}
__device__ __forceinline__ void cp16(unsigned dst, const void* src) {
    asm volatile("cp.async.cg.shared.global [%0], [%1], 16;\n" :: "r"(dst), "l"(src));
}
__device__ __forceinline__ void cp_commit() {
    asm volatile("cp.async.commit_group;\n" ::: "memory");
}
template <int N>
__device__ __forceinline__ void cp_wait() {
    asm volatile("cp.async.wait_group %0;\n" :: "n"(N) : "memory");
}
__device__ __forceinline__ void stg_cs_v2(float2* p, float2 v) {
    asm volatile("st.global.cs.v2.f32 [%0], {%1, %2};\n" :: "l"(p), "f"(v.x), "f"(v.y));
}

// sigmoid(z) = 0.5 * tanh(0.5 z) + 0.5   -> 1 MUFU.TANH + FMUL + FFMA
__device__ __forceinline__ float sigmoid_t(float z) {
    float th;
    asm("tanh.approx.f32 %0, %1;" : "=f"(th) : "f"(z * 0.5f));
    return fmaf(th, 0.5f, 0.5f);
}

__global__ __launch_bounds__(THREADS, 5)
void mlp3_kernel(const float* __restrict__ x,
                 const float* __restrict__ W1,   // [HID, IN]
                 const float* __restrict__ W2,   // [HID, HID]
                 const float* __restrict__ W5,   // [OUT, HID]
                 float* __restrict__ out,        // [B, OUT]
                 int B, int nwt)
{
    __shared__ __align__(16) float sW1[HID * IN_DIM];
    __shared__ __align__(16) float sW2[HID * 8];
    __shared__ __align__(16) float sW5[OUT_DIM * 8];
    // per-warp double buffers: [NWARPS][2][WT_FLOATS]
    extern __shared__ __align__(16) float sX[];

    const int t = threadIdx.x;
    const int w = t >> 5;
    const int l = t & 31;

    if (t < HID * IN_DIM) sW1[t] = W1[t];
    if (t < HID * 8)      sW2[t] = ((t & 7) < HID) ? W2[(t >> 3) * HID + (t & 7)] : 0.0f;
    if (t < OUT_DIM * 8)  sW5[t] = ((t & 7) < HID) ? W5[(t >> 3) * HID + (t & 7)] : 0.0f;

    const size_t total_f4 = ((size_t)B * IN_DIM) >> 2;
    float* mybuf0 = &sX[(size_t)(w * 2) * WT_FLOATS];

    // warp-local stage: 10 contiguous float4 per lane (fully coalesced)
    auto stage = [&](int wt, int buf) {
        size_t base_f4 = (size_t)wt * WT_F4;
        const float4* src = reinterpret_cast<const float4*>(x) + base_f4;
        unsigned dst = smem_u32(mybuf0 + (size_t)buf * WT_FLOATS);
#pragma unroll
        for (int q = 0; q < F4_PL; ++q) {
            int idx = l + q * 32;
            if (base_f4 + (size_t)idx < total_f4)
                cp16(dst + (unsigned)idx * 16, src + idx);
        }
    };

    const int wstride = gridDim.x * NWARPS;
    int wt = blockIdx.x * NWARPS + w;

    if (wt < nwt) stage(wt, 0);
    cp_commit();

    __syncthreads();   // weights visible (once, before the loop)

    int buf = 0;
    for (; wt < nwt; wt += wstride, buf ^= 1) {
        int nxt = wt + wstride;
        if (nxt < nwt) stage(nxt, buf ^ 1);
        cp_commit();
        cp_wait<1>();          // our own warp's current tile is complete
        __syncwarp();          // lane-visibility of peer lanes' staged bytes

        const float* xb = mybuf0 + (size_t)buf * WT_FLOATS;
        const int r0 = wt * WT_ROWS + l;        // row A
        const int r1 = r0 + 32;                 // row B

        // ---- both rows from smem: 2 x 5 LDS.128, conflict-free in-phase ----
        float4 xa[5], xbv[5];
        const float4* pa = reinterpret_cast<const float4*>(&xb[l * IN_DIM]);
        const float4* pb = reinterpret_cast<const float4*>(&xb[(l + 32) * IN_DIM]);
#pragma unroll
        for (int q = 0; q < 5; ++q) { xa[q] = pa[q]; xbv[q] = pb[q]; }

        // ---- layer 1 (weights shared across both rows) ----
        float h1a[6], h1b[6];
#pragma unroll
        for (int j = 0; j < HID; ++j) {
            const float4* wr = reinterpret_cast<const float4*>(&sW1[j * IN_DIM]);
            float a = 0.0f, b = 0.0f;
#pragma unroll
            for (int q = 0; q < 5; ++q) {
                float4 wv = wr[q];
                a = fmaf(xa[q].x,  wv.x, a); b = fmaf(xbv[q].x, wv.x, b);
                a = fmaf(xa[q].y,  wv.y, a); b = fmaf(xbv[q].y, wv.y, b);
                a = fmaf(xa[q].z,  wv.z, a); b = fmaf(xbv[q].z, wv.z, b);
                a = fmaf(xa[q].w,  wv.w, a); b = fmaf(xbv[q].w, wv.w, b);
            }
            h1a[j] = sigmoid_t(a);
            h1b[j] = sigmoid_t(b);
        }

        // ---- layer 2 ----
        float h2a[6], h2b[6];
#pragma unroll
        for (int j = 0; j < HID; ++j) {
            const float4* wr = reinterpret_cast<const float4*>(&sW2[j * 8]);
            float4 w0 = wr[0], w1 = wr[1];
            float a = 0.0f, b = 0.0f;
            a = fmaf(h1a[0], w0.x, a); b = fmaf(h1b[0], w0.x, b);
            a = fmaf(h1a[1], w0.y, a); b = fmaf(h1b[1], w0.y, b);
            a = fmaf(h1a[2], w0.z, a); b = fmaf(h1b[2], w0.z, b);
            a = fmaf(h1a[3], w0.w, a); b = fmaf(h1b[3], w0.w, b);
            a = fmaf(h1a[4], w1.x, a); b = fmaf(h1b[4], w1.x, b);
            a = fmaf(h1a[5], w1.y, a); b = fmaf(h1b[5], w1.y, b);
            h2a[j] = sigmoid_t(a);
            h2b[j] = sigmoid_t(b);
        }

        // ---- layer 3 (linear) ----
        float oa[OUT_DIM], ob[OUT_DIM];
#pragma unroll
        for (int j = 0; j < OUT_DIM; ++j) {
            const float4* wr = reinterpret_cast<const float4*>(&sW5[j * 8]);
            float4 w0 = wr[0], w1 = wr[1];
            float a = 0.0f, b = 0.0f;
            a = fmaf(h2a[0], w0.x, a); b = fmaf(h2b[0], w0.x, b);
            a = fmaf(h2a[1], w0.y, a); b = fmaf(h2b[1], w0.y, b);
            a = fmaf(h2a[2], w0.z, a); b = fmaf(h2b[2], w0.z, b);
            a = fmaf(h2a[3], w0.w, a); b = fmaf(h2b[3], w0.w, b);
            a = fmaf(h2a[4], w1.x, a); b = fmaf(h2b[4], w1.x, b);
            a = fmaf(h2a[5], w1.y, a); b = fmaf(h2b[5], w1.y, b);
            oa[j] = a; ob[j] = b;
        }

        if (r0 < B) {
            float2* op = reinterpret_cast<float2*>(out + (size_t)r0 * OUT_DIM);
            stg_cs_v2(op + 0, make_float2(oa[0], oa[1]));
            stg_cs_v2(op + 1, make_float2(oa[2], oa[3]));
            stg_cs_v2(op + 2, make_float2(oa[4], oa[5]));
        }
        if (r1 < B) {
            float2* op = reinterpret_cast<float2*>(out + (size_t)r1 * OUT_DIM);
            stg_cs_v2(op + 0, make_float2(ob[0], ob[1]));
            stg_cs_v2(op + 1, make_float2(ob[2], ob[3]));
            stg_cs_v2(op + 2, make_float2(ob[4], ob[5]));
        }
        // no block barrier: buffer ownership is warp-private; same-warp
        // program order makes the WAR on restage safe.
    }
}

extern "C" void kernel_launch(void* const* d_in, const int* in_sizes, int n_in,
                              void* d_out, int out_size)
{
    const float* x  = (const float*)d_in[0];
    const float* W1 = (const float*)d_in[1];
    const float* W2 = (const float*)d_in[2];
    const float* W5 = (const float*)d_in[3];
    float* out = (float*)d_out;

    const int B = in_sizes[0] / IN_DIM;
    const int nwt = (B + WT_ROWS - 1) / WT_ROWS;

    const size_t smem_bytes = (size_t)NWARPS * 2 * WT_FLOATS * sizeof(float);  // 40 KB
    static bool attr_set = false;
    if (!attr_set) {
        cudaFuncSetAttribute(mlp3_kernel,
                             cudaFuncAttributeMaxDynamicSharedMemorySize,
                             (int)smem_bytes);
        attr_set = true;
    }

    int blocks = 148 * 5;                 // persistent: 5 CTAs/SM, 20 warp-pipelines
    int max_blocks = (nwt + NWARPS - 1) / NWARPS;
    if (blocks > max_blocks) blocks = max_blocks;
    if (blocks < 1) blocks = 1;

    mlp3_kernel<<<blocks, THREADS, smem_bytes>>>(x, W1, W2, W5, out, B, nwt);
}